// round 3
// baseline (speedup 1.0000x reference)
#include <cuda_runtime.h>

#define D          1024
#define NHEAD      10004
#define SHORTLIST  10000
#define NPROJ      960
#define NCL        90000
#define NTGT       4096

#define PROJ_BLOCKS 120                  // 960 rows / 8 warps
#define HEAD_BLOCKS 1251                 // ceil(10004 / 8)
#define CL_BLOCKS   11250                // 90000 / 8
#define NBLOCKS     (PROJ_BLOCKS + HEAD_BLOCKS + CL_BLOCKS)
#define CL_BASE     (PROJ_BLOCKS + HEAD_BLOCKS)

// Scratch (zero-initialized device globals; counters reset by the loss block)
__device__ float g_head_logits[NHEAD];
__device__ float g_proj[NPROJ];
__device__ float g_cl[NCL];
__device__ float g_sumexp[5];
__device__ int   g_proj_ctr;
__device__ int   g_done_ctr;

__device__ __forceinline__ float warp_sum(float v) {
#pragma unroll
    for (int o = 16; o; o >>= 1) v += __shfl_xor_sync(0xffffffffu, v, o);
    return v;
}

__global__ void __launch_bounds__(256)
fused_kernel(const float* __restrict__ feature,
             const int*   __restrict__ targets,
             const float* __restrict__ head_w,
             const float* __restrict__ t0p, const float* __restrict__ t0w,
             const float* __restrict__ t1p, const float* __restrict__ t1w,
             const float* __restrict__ t2p, const float* __restrict__ t2w,
             const float* __restrict__ t3p, const float* __restrict__ t3w,
             float* __restrict__ out) {
    __shared__ float sv[D];        // feature (head/proj) or proj slice (cluster)
    __shared__ float s_sum[5];
    __shared__ int   s_last;

    const int tid  = threadIdx.x;
    const int lane = tid & 31;
    const int warp = tid >> 5;
    const int bid  = blockIdx.x;

    if (tid < 5) s_sum[tid] = 0.f;
    if (tid == 5) s_last = 0;

    if (bid < PROJ_BLOCKS) {
        // ---- projection rows: proj = t_ip @ feature ----
        for (int i = tid; i < D; i += 256) sv[i] = feature[i];
        __syncthreads();
        int row = bid * 8 + warp;
        const float* w;
        if      (row < 512) w = t0p + (size_t)row * D;
        else if (row < 768) w = t1p + (size_t)(row - 512) * D;
        else if (row < 896) w = t2p + (size_t)(row - 768) * D;
        else                w = t3p + (size_t)(row - 896) * D;
        const float4* w4 = (const float4*)w;
        const float4* f4 = (const float4*)sv;
        float acc = 0.f;
#pragma unroll
        for (int j = 0; j < 8; j++) {
            float4 a = w4[lane + j * 32];
            float4 b = f4[lane + j * 32];
            acc += a.x * b.x + a.y * b.y + a.z * b.z + a.w * b.w;
        }
        acc = warp_sum(acc);
        if (lane == 0) g_proj[row] = acc;
        __threadfence();
        __syncthreads();
        if (tid == 0) atomicAdd(&g_proj_ctr, 1);
    } else if (bid < CL_BASE) {
        // ---- head rows ----
        for (int i = tid; i < D; i += 256) sv[i] = feature[i];
        __syncthreads();
        int row = (bid - PROJ_BLOCKS) * 8 + warp;
        if (row < NHEAD) {
            const float4* w4 = (const float4*)(head_w + (size_t)row * D);
            const float4* v4 = (const float4*)sv;
            float acc = 0.f;
#pragma unroll
            for (int j = 0; j < 8; j++) {
                float4 a = w4[lane + j * 32];
                float4 b = v4[lane + j * 32];
                acc += a.x * b.x + a.y * b.y + a.z * b.z + a.w * b.w;
            }
            acc = warp_sum(acc);
            if (lane == 0) {
                g_head_logits[row] = acc;
                atomicAdd(&s_sum[0], __expf(acc));
            }
        }
    } else {
        // ---- cluster rows (need proj) ----
        int r0 = (bid - CL_BASE) * 8;   // first vocab-tail index of this block
        int seg, len, proj_off;
        const float* wmat;
        size_t lrow;
        if (r0 < 10000)      { seg = 1; len = 512; wmat = t0w; lrow = r0;          proj_off = 0;   }
        else if (r0 < 30000) { seg = 2; len = 256; wmat = t1w; lrow = r0 - 10000;  proj_off = 512; }
        else if (r0 < 70000) { seg = 3; len = 128; wmat = t2w; lrow = r0 - 30000;  proj_off = 768; }
        else                 { seg = 4; len =  64; wmat = t3w; lrow = r0 - 70000;  proj_off = 896; }

        if (tid == 0) {
            while (((volatile int*)&g_proj_ctr)[0] < PROJ_BLOCKS) { }
        }
        __syncthreads();
        for (int i = tid; i < len; i += 256) sv[i] = __ldcg(&g_proj[proj_off + i]);
        __syncthreads();

        const float4* w4 = (const float4*)(wmat + (lrow + warp) * (size_t)len);
        const float4* v4 = (const float4*)sv;
        int n4 = len >> 2;
        float acc = 0.f;
        for (int j = lane; j < n4; j += 32) {
            float4 a = w4[j];
            float4 b = v4[j];
            acc += a.x * b.x + a.y * b.y + a.z * b.z + a.w * b.w;
        }
        acc = warp_sum(acc);
        if (lane == 0) {
            g_cl[r0 + warp] = acc;
            atomicAdd(&s_sum[seg], __expf(acc));
        }
    }

    // ---- flush per-block sum-exp, count completion ----
    __syncthreads();
    if (tid < 5 && s_sum[tid] != 0.f) {
        atomicAdd(&g_sumexp[tid], s_sum[tid]);
    }
    __threadfence();
    __syncthreads();
    if (tid == 0) {
        int old = atomicAdd(&g_done_ctr, 1);
        if (old == NBLOCKS - 1) s_last = 1;
    }
    __syncthreads();
    if (!s_last) return;

    // ---- last block: loss over 4096 targets ----
    __shared__ float s_lse[5];
    __shared__ float sh[8];
    if (tid < 5) s_lse[tid] = logf(__ldcg(&g_sumexp[tid]));
    __syncthreads();
    float lse_h = s_lse[0];

    float local = 0.f;
    const int4* t4p = (const int4*)targets;
#pragma unroll
    for (int k = 0; k < 4; k++) {          // 4096 / (256 threads * 4/int4) = 4
        int4 t4 = t4p[tid + k * 256];
        int ts[4] = {t4.x, t4.y, t4.z, t4.w};
#pragma unroll
        for (int m = 0; m < 4; m++) {
            int t = ts[m];
            float lp;
            if (t < SHORTLIST) {
                lp = __ldcg(&g_head_logits[t]) - lse_h;
            } else {
                int ci;
                if      (t < 20000) ci = 0;
                else if (t < 40000) ci = 1;
                else if (t < 80000) ci = 2;
                else                ci = 3;
                lp = __ldcg(&g_cl[t - SHORTLIST]) - s_lse[1 + ci]
                   + __ldcg(&g_head_logits[SHORTLIST + ci]) - lse_h;
            }
            local += lp;
        }
    }
    local = warp_sum(local);
    if (lane == 0) sh[warp] = local;
    __syncthreads();
    if (warp == 0) {
        float v = (lane < 8) ? sh[lane] : 0.f;
        v = warp_sum(v);
        if (lane == 0) out[0] = -v / (float)NTGT;
    }

    // ---- reset scratch for the next replay (deterministic) ----
    __syncthreads();
    if (tid == 0) { g_done_ctr = 0; g_proj_ctr = 0; }
    if (tid < 5) g_sumexp[tid] = 0.f;
}

extern "C" void kernel_launch(void* const* d_in, const int* in_sizes, int n_in,
                              void* d_out, int out_size) {
    const float* feature = (const float*)d_in[0];
    const int*   targets = (const int*)  d_in[1];
    const float* head_w  = (const float*)d_in[2];
    const float* t0p     = (const float*)d_in[3];
    const float* t0w     = (const float*)d_in[4];
    const float* t1p     = (const float*)d_in[5];
    const float* t1w     = (const float*)d_in[6];
    const float* t2p     = (const float*)d_in[7];
    const float* t2w     = (const float*)d_in[8];
    const float* t3p     = (const float*)d_in[9];
    const float* t3w     = (const float*)d_in[10];

    fused_kernel<<<NBLOCKS, 256>>>(feature, targets, head_w,
                                   t0p, t0w, t1p, t1w, t2p, t2w, t3p, t3w,
                                   (float*)d_out);
}

// round 4
// speedup vs baseline: 1.4437x; 1.4437x over previous
#include <cuda_runtime.h>

#define D          1024
#define NHEAD      10004
#define SHORTLIST  10000
#define NPROJ      960
#define NCL        90000
#define NTGT       4096

#define LB_THREADS 512
#define LB_WARPS   16
#define HEAD_BLOCKS ((NHEAD + LB_WARPS - 1) / LB_WARPS)   // 626
#define CL_BLOCKS   (NCL / LB_WARPS)                      // 5625
#define NROW_BLOCKS (HEAD_BLOCKS + CL_BLOCKS)

// Scratch (allocation-free __device__ globals)
__device__ float g_head_logits[NHEAD];
__device__ float g_proj[NPROJ];
__device__ float g_cl[NCL];       // cluster logits, vocab order (t - 10000)
__device__ float g_sumexp[5];     // zeroed by proj_kernel each replay

__device__ __forceinline__ float warp_sum(float v) {
#pragma unroll
    for (int o = 16; o; o >>= 1) v += __shfl_xor_sync(0xffffffffu, v, o);
    return v;
}

// ---------------------------------------------------------------------------
// K0: tail projections, block-per-row (960 blocks x 128 threads)
//     also zeroes g_sumexp for this replay
// ---------------------------------------------------------------------------
__global__ void __launch_bounds__(128)
proj_kernel(const float* __restrict__ feature,
            const float* __restrict__ t0p, const float* __restrict__ t1p,
            const float* __restrict__ t2p, const float* __restrict__ t3p) {
    const int tid = threadIdx.x, lane = tid & 31, warp = tid >> 5;
    const int row = blockIdx.x;
    if (row == 0 && tid < 5) g_sumexp[tid] = 0.f;

    const float* w;
    if      (row < 512) w = t0p + (size_t)row * D;
    else if (row < 768) w = t1p + (size_t)(row - 512) * D;
    else if (row < 896) w = t2p + (size_t)(row - 768) * D;
    else                w = t3p + (size_t)(row - 896) * D;

    const float4* w4 = (const float4*)w;
    const float4* f4 = (const float4*)feature;
    float acc = 0.f;
#pragma unroll
    for (int j = 0; j < 2; j++) {          // 1024/4 = 256 float4, 128 threads
        float4 a = w4[tid + j * 128];
        float4 b = f4[tid + j * 128];
        acc += a.x * b.x + a.y * b.y + a.z * b.z + a.w * b.w;
    }
    acc = warp_sum(acc);
    __shared__ float sh[4];
    if (lane == 0) sh[warp] = acc;
    __syncthreads();
    if (tid == 0) g_proj[row] = sh[0] + sh[1] + sh[2] + sh[3];
}

// ---------------------------------------------------------------------------
// K1: all logits + fused per-segment sum(exp). 16 warps/block, warp-per-row.
// Each block is segment-uniform (boundaries 10000/30000/70000 are
// multiples of 16), so it loads ONLY the vector slice it needs.
// ---------------------------------------------------------------------------
__global__ void __launch_bounds__(LB_THREADS)
logits_kernel(const float* __restrict__ feature,
              const float* __restrict__ head_w,
              const float* __restrict__ t0w, const float* __restrict__ t1w,
              const float* __restrict__ t2w, const float* __restrict__ t3w) {
    __shared__ float sv[D];
    __shared__ float s_sum;
    const int tid = threadIdx.x, lane = tid & 31, warp = tid >> 5;
    const int bid = blockIdx.x;
    if (tid == 0) s_sum = 0.f;

    float acc = 0.f;
    int seg;
    bool valid = true;

    if (bid < HEAD_BLOCKS) {
        seg = 0;
        for (int i = tid; i < D; i += LB_THREADS) sv[i] = feature[i];
        __syncthreads();
        int row = bid * LB_WARPS + warp;
        if (row < NHEAD) {
            const float4* w4 = (const float4*)(head_w + (size_t)row * D);
            const float4* v4 = (const float4*)sv;
#pragma unroll
            for (int j = 0; j < 8; j++) {
                float4 a = w4[lane + j * 32];
                float4 b = v4[lane + j * 32];
                acc += a.x * b.x + a.y * b.y + a.z * b.z + a.w * b.w;
            }
            acc = warp_sum(acc);
            if (lane == 0) g_head_logits[row] = acc;
        } else {
            valid = false;
        }
    } else {
        int r0 = (bid - HEAD_BLOCKS) * LB_WARPS;     // vocab-tail base index
        int len, proj_off;
        const float* wmat;
        size_t lbase;
        if (r0 < 10000)      { seg = 1; len = 512; wmat = t0w; lbase = r0;         proj_off = 0;   }
        else if (r0 < 30000) { seg = 2; len = 256; wmat = t1w; lbase = r0 - 10000; proj_off = 512; }
        else if (r0 < 70000) { seg = 3; len = 128; wmat = t2w; lbase = r0 - 30000; proj_off = 768; }
        else                 { seg = 4; len =  64; wmat = t3w; lbase = r0 - 70000; proj_off = 896; }

        if (tid < len) sv[tid] = g_proj[proj_off + tid];
        __syncthreads();

        const float4* w4 = (const float4*)(wmat + (lbase + warp) * (size_t)len);
        const float4* v4 = (const float4*)sv;
        const int n4 = len >> 2;
        if (n4 >= 32) {
#pragma unroll 4
            for (int j = lane; j < n4; j += 32) {
                float4 a = w4[j];
                float4 b = v4[j];
                acc += a.x * b.x + a.y * b.y + a.z * b.z + a.w * b.w;
            }
        } else if (lane < n4) {   // len == 64
            float4 a = w4[lane];
            float4 b = v4[lane];
            acc += a.x * b.x + a.y * b.y + a.z * b.z + a.w * b.w;
        }
        acc = warp_sum(acc);
        if (lane == 0) g_cl[r0 + warp] = acc;
    }

    if (lane == 0 && valid) atomicAdd(&s_sum, __expf(acc));
    __syncthreads();
    if (tid == 0) atomicAdd(&g_sumexp[seg], s_sum);
}

// ---------------------------------------------------------------------------
// K2: gather targets, mean, negate -> scalar.  lse = log(sumexp)
// ---------------------------------------------------------------------------
__global__ void __launch_bounds__(1024)
loss_kernel(const int* __restrict__ targets, float* __restrict__ out) {
    __shared__ float sh[32];
    __shared__ float s_lse[5];
    const int tid = threadIdx.x, lane = tid & 31, warp = tid >> 5;

    if (tid < 5) s_lse[tid] = logf(g_sumexp[tid]);
    __syncthreads();
    const float lse_h = s_lse[0];

    int4 t4 = ((const int4*)targets)[tid];   // 4096 / 1024 = 1 int4 each
    int ts[4] = {t4.x, t4.y, t4.z, t4.w};
    float local = 0.f;
#pragma unroll
    for (int k = 0; k < 4; k++) {
        int t = ts[k];
        float lp;
        if (t < SHORTLIST) {
            lp = g_head_logits[t] - lse_h;
        } else {
            int ci;
            if      (t < 20000) ci = 0;
            else if (t < 40000) ci = 1;
            else if (t < 80000) ci = 2;
            else                ci = 3;
            lp = g_cl[t - SHORTLIST] - s_lse[1 + ci]
               + g_head_logits[SHORTLIST + ci] - lse_h;
        }
        local += lp;
    }
    local = warp_sum(local);
    if (lane == 0) sh[warp] = local;
    __syncthreads();
    if (warp == 0) {
        float v = (lane < 32) ? sh[lane] : 0.f;
        v = warp_sum(v);
        if (lane == 0) out[0] = -v / (float)NTGT;
    }
}

// ---------------------------------------------------------------------------
extern "C" void kernel_launch(void* const* d_in, const int* in_sizes, int n_in,
                              void* d_out, int out_size) {
    const float* feature = (const float*)d_in[0];
    const int*   targets = (const int*)  d_in[1];
    const float* head_w  = (const float*)d_in[2];
    const float* t0p     = (const float*)d_in[3];
    const float* t0w     = (const float*)d_in[4];
    const float* t1p     = (const float*)d_in[5];
    const float* t1w     = (const float*)d_in[6];
    const float* t2p     = (const float*)d_in[7];
    const float* t2w     = (const float*)d_in[8];
    const float* t3p     = (const float*)d_in[9];
    const float* t3w     = (const float*)d_in[10];

    proj_kernel<<<NPROJ, 128>>>(feature, t0p, t1p, t2p, t3p);
    logits_kernel<<<NROW_BLOCKS, LB_THREADS>>>(feature, head_w, t0w, t1w, t2w, t3w);
    loss_kernel<<<1, 1024>>>(targets, (float*)d_out);
}

// round 5
// speedup vs baseline: 1.9170x; 1.3279x over previous
#include <cuda_runtime.h>

#define D          1024
#define NHEAD      10004
#define SHORTLIST  10000
#define NPROJ      960
#define NCL        90000
#define NTGT       4096

#define LB_THREADS 512
#define LB_WARPS   16
#define HEAD_BLOCKS ((NHEAD + LB_WARPS - 1) / LB_WARPS)   // 626
#define CL_CHUNKS   32500    // 10000 + 10000 + 10000 + 2500 (2KB chunks)
#define CL_BLOCKS   ((CL_CHUNKS + LB_WARPS - 1) / LB_WARPS) // 2032
#define NROW_BLOCKS (HEAD_BLOCKS + CL_BLOCKS)

// Scratch (allocation-free __device__ globals)
__device__ float g_head_logits[NHEAD];
__device__ float g_proj[NPROJ];
__device__ float g_cl[NCL];       // cluster logits, vocab order (t - 10000)
__device__ float g_sumexp[5];     // zeroed by proj_kernel each replay

__device__ __forceinline__ float warp_sum(float v) {
#pragma unroll
    for (int o = 16; o; o >>= 1) v += __shfl_xor_sync(0xffffffffu, v, o);
    return v;
}
__device__ __forceinline__ float half16_sum(float v) {   // reduce within 16-lane halves
#pragma unroll
    for (int o = 8; o; o >>= 1) v += __shfl_xor_sync(0xffffffffu, v, o);
    return v;
}
__device__ __forceinline__ float dot4(float4 a, float4 b) {
    return a.x * b.x + a.y * b.y + a.z * b.z + a.w * b.w;
}

// ---------------------------------------------------------------------------
// K0: tail projections, warp-per-row, MLP=8, no smem (feature hits L1/L2)
//     also zeroes g_sumexp for this replay
// ---------------------------------------------------------------------------
__global__ void __launch_bounds__(256)
proj_kernel(const float* __restrict__ feature,
            const float* __restrict__ t0p, const float* __restrict__ t1p,
            const float* __restrict__ t2p, const float* __restrict__ t3p) {
    const int tid = threadIdx.x, lane = tid & 31, warp = tid >> 5;
    const int row = blockIdx.x * 8 + warp;
    if (blockIdx.x == 0 && tid < 5) g_sumexp[tid] = 0.f;

    const float* w;
    if      (row < 512) w = t0p + (size_t)row * D;
    else if (row < 768) w = t1p + (size_t)(row - 512) * D;
    else if (row < 896) w = t2p + (size_t)(row - 768) * D;
    else                w = t3p + (size_t)(row - 896) * D;

    const float4* w4 = (const float4*)w;
    const float4* f4 = (const float4*)feature;
    float acc = 0.f;
#pragma unroll
    for (int j = 0; j < 8; j++)
        acc += dot4(w4[lane + j * 32], f4[lane + j * 32]);
    acc = warp_sum(acc);
    if (lane == 0) g_proj[row] = acc;
}

// ---------------------------------------------------------------------------
// K1: all logits + fused per-segment sum(exp).
// Head: warp-per-row (MLP=8). Clusters: warp-per-2KB-chunk (MLP=4):
//   chunk = 128 float4; rows/chunk = 1 (t0,len512) / 2 (t1,256) / 4 (t2,128) / 8 (t3,64)
//   lane loads idx = lane + 32k (k=0..3): coalesced global, conflict-free smem.
// Chunk-space: t0 [0,10000) t1 [10000,20000) t2 [20000,30000) t3 [30000,32500)
// All boundaries are multiples of 16 -> blocks are segment-uniform.
// ---------------------------------------------------------------------------
__global__ void __launch_bounds__(LB_THREADS)
logits_kernel(const float* __restrict__ feature,
              const float* __restrict__ head_w,
              const float* __restrict__ t0w, const float* __restrict__ t1w,
              const float* __restrict__ t2w, const float* __restrict__ t3w) {
    __shared__ float sv[D];
    __shared__ float s_sum;
    const int tid = threadIdx.x, lane = tid & 31, warp = tid >> 5;
    const int bid = blockIdx.x;
    if (tid == 0) s_sum = 0.f;

    if (bid < HEAD_BLOCKS) {
        for (int i = tid; i < D; i += LB_THREADS) sv[i] = feature[i];
        __syncthreads();
        int row = bid * LB_WARPS + warp;
        if (row < NHEAD) {
            const float4* w4 = (const float4*)(head_w + (size_t)row * D);
            const float4* v4 = (const float4*)sv;
            float acc = 0.f;
#pragma unroll
            for (int j = 0; j < 8; j++)
                acc += dot4(w4[lane + j * 32], v4[lane + j * 32]);
            acc = warp_sum(acc);
            if (lane == 0) {
                g_head_logits[row] = acc;
                atomicAdd(&s_sum, __expf(acc));
            }
        }
        __syncthreads();
        if (tid == 0) atomicAdd(&g_sumexp[0], s_sum);
        return;
    }

    const int c0 = (bid - HEAD_BLOCKS) * LB_WARPS;   // global chunk base of block
    int seg, lenf, proj_off, chunk;                  // chunk = segment-local
    const float* wmat;
    if (c0 < 10000)      { seg = 1; lenf = 512; wmat = t0w; chunk = c0 + warp;         proj_off = 0;   }
    else if (c0 < 20000) { seg = 2; lenf = 256; wmat = t1w; chunk = c0 - 10000 + warp; proj_off = 512; }
    else if (c0 < 30000) { seg = 3; lenf = 128; wmat = t2w; chunk = c0 - 20000 + warp; proj_off = 768; }
    else                 { seg = 4; lenf =  64; wmat = t3w; chunk = c0 - 30000 + warp; proj_off = 896; }

    for (int i = tid; i < lenf; i += LB_THREADS) sv[i] = g_proj[proj_off + i];
    __syncthreads();

    const bool valid = (c0 + warp) < CL_CHUNKS;      // only t3's last block masks
    float a0 = 0.f, a1 = 0.f, a2 = 0.f, a3 = 0.f;
    if (valid) {
        const float4* w4 = (const float4*)wmat + (size_t)chunk * 128;
        const float4* v4 = (const float4*)sv;
        const int vm = (lenf >> 2) - 1;              // power-of-two mask
        float4 w0 = w4[lane];       float4 w1 = w4[lane + 32];
        float4 w2 = w4[lane + 64];  float4 w3 = w4[lane + 96];
        a0 = dot4(w0, v4[lane & vm]);
        a1 = dot4(w1, v4[(lane + 32) & vm]);
        a2 = dot4(w2, v4[(lane + 64) & vm]);
        a3 = dot4(w3, v4[(lane + 96) & vm]);
    }

    if (valid) {
        float es = 0.f;
        if (seg == 1) {                       // 1 row/chunk
            float r = warp_sum(a0 + a1 + a2 + a3);
            if (lane == 0) { g_cl[chunk] = r; es = __expf(r); }
        } else if (seg == 2) {                // 2 rows/chunk
            float r0 = warp_sum(a0 + a1);
            float r1 = warp_sum(a2 + a3);
            if (lane == 0) {
                *(float2*)&g_cl[10000 + chunk * 2] = make_float2(r0, r1);
                es = __expf(r0) + __expf(r1);
            }
        } else if (seg == 3) {                // 4 rows/chunk
            float r0 = warp_sum(a0), r1 = warp_sum(a1);
            float r2 = warp_sum(a2), r3 = warp_sum(a3);
            if (lane == 0) {
                *(float4*)&g_cl[30000 + chunk * 4] = make_float4(r0, r1, r2, r3);
                es = __expf(r0) + __expf(r1) + __expf(r2) + __expf(r3);
            }
        } else {                              // 8 rows/chunk (2 per k, lane halves)
            float h0 = half16_sum(a0), h1 = half16_sum(a1);
            float h2 = half16_sum(a2), h3 = half16_sum(a3);
            float o0 = __shfl_sync(0xffffffffu, h0, 16);
            float o1 = __shfl_sync(0xffffffffu, h1, 16);
            float o2 = __shfl_sync(0xffffffffu, h2, 16);
            float o3 = __shfl_sync(0xffffffffu, h3, 16);
            if (lane == 0) {
                float* p = &g_cl[70000 + chunk * 8];
                *(float4*)p       = make_float4(h0, o0, h1, o1);
                *(float4*)(p + 4) = make_float4(h2, o2, h3, o3);
                es = __expf(h0) + __expf(o0) + __expf(h1) + __expf(o1)
                   + __expf(h2) + __expf(o2) + __expf(h3) + __expf(o3);
            }
        }
        if (lane == 0) atomicAdd(&s_sum, es);
    }
    __syncthreads();
    if (tid == 0) atomicAdd(&g_sumexp[seg], s_sum);
}

// ---------------------------------------------------------------------------
// K2: gather targets, mean, negate -> scalar.  lse = log(sumexp)
// ---------------------------------------------------------------------------
__global__ void __launch_bounds__(1024)
loss_kernel(const int* __restrict__ targets, float* __restrict__ out) {
    __shared__ float sh[32];
    __shared__ float s_lse[5];
    const int tid = threadIdx.x, lane = tid & 31, warp = tid >> 5;

    if (tid < 5) s_lse[tid] = logf(g_sumexp[tid]);
    __syncthreads();
    const float lse_h = s_lse[0];

    int4 t4 = ((const int4*)targets)[tid];   // 4096 / 1024 = 1 int4 each
    int ts[4] = {t4.x, t4.y, t4.z, t4.w};
    float local = 0.f;
#pragma unroll
    for (int k = 0; k < 4; k++) {
        int t = ts[k];
        float lp;
        if (t < SHORTLIST) {
            lp = g_head_logits[t] - lse_h;
        } else {
            int ci;
            if      (t < 20000) ci = 0;
            else if (t < 40000) ci = 1;
            else if (t < 80000) ci = 2;
            else                ci = 3;
            lp = g_cl[t - SHORTLIST] - s_lse[1 + ci]
               + g_head_logits[SHORTLIST + ci] - lse_h;
        }
        local += lp;
    }
    local = warp_sum(local);
    if (lane == 0) sh[warp] = local;
    __syncthreads();
    if (warp == 0) {
        float v = sh[lane];
        v = warp_sum(v);
        if (lane == 0) out[0] = -v / (float)NTGT;
    }
}

// ---------------------------------------------------------------------------
extern "C" void kernel_launch(void* const* d_in, const int* in_sizes, int n_in,
                              void* d_out, int out_size) {
    const float* feature = (const float*)d_in[0];
    const int*   targets = (const int*)  d_in[1];
    const float* head_w  = (const float*)d_in[2];
    const float* t0p     = (const float*)d_in[3];
    const float* t0w     = (const float*)d_in[4];
    const float* t1p     = (const float*)d_in[5];
    const float* t1w     = (const float*)d_in[6];
    const float* t2p     = (const float*)d_in[7];
    const float* t2w     = (const float*)d_in[8];
    const float* t3p     = (const float*)d_in[9];
    const float* t3w     = (const float*)d_in[10];

    proj_kernel<<<NPROJ / 8, 256>>>(feature, t0p, t1p, t2p, t3p);
    logits_kernel<<<NROW_BLOCKS, LB_THREADS>>>(feature, head_w, t0w, t1w, t2w, t3w);
    loss_kernel<<<1, 1024>>>(targets, (float*)d_out);
}

// round 6
// speedup vs baseline: 1.9715x; 1.0285x over previous
#include <cuda_runtime.h>

#define D          1024
#define NHEAD      10004
#define SHORTLIST  10000
#define NPROJ      960
#define NCL        90000
#define NTGT       4096

#define FK_THREADS 512
#define FK_WARPS   16
#define PROJ_BLOCKS 60                                     // 960 rows / 16 warps
#define HEAD_BLOCKS ((NHEAD + FK_WARPS - 1) / FK_WARPS)    // 626
#define CL_CHUNKS   32500    // 10000 + 10000 + 10000 + 2500 (2KB chunks)
#define CL_BLOCKS   ((CL_CHUNKS + FK_WARPS - 1) / FK_WARPS) // 2032
#define HEAD_BASE   PROJ_BLOCKS
#define CL_BASE     (PROJ_BLOCKS + HEAD_BLOCKS)
#define NBLOCKS     (PROJ_BLOCKS + HEAD_BLOCKS + CL_BLOCKS)

// Scratch (allocation-free __device__ globals; counters reset by loss_kernel)
__device__ float g_head_logits[NHEAD];
__device__ float g_proj[NPROJ];
__device__ float g_cl[NCL];       // cluster logits, vocab order (t - 10000)
__device__ float g_sumexp[5];
__device__ int   g_proj_ctr;

__device__ __forceinline__ float warp_sum(float v) {
#pragma unroll
    for (int o = 16; o; o >>= 1) v += __shfl_xor_sync(0xffffffffu, v, o);
    return v;
}
__device__ __forceinline__ float half16_sum(float v) {   // reduce within 16-lane halves
#pragma unroll
    for (int o = 8; o; o >>= 1) v += __shfl_xor_sync(0xffffffffu, v, o);
    return v;
}
__device__ __forceinline__ float dot4(float4 a, float4 b) {
    return a.x * b.x + a.y * b.y + a.z * b.z + a.w * b.w;
}

// ---------------------------------------------------------------------------
// Fused kernel. Grid = [proj 60 | head 626 | cluster 2032] blocks, 512 thr.
// Proj blocks are wave-1 resident (60 < 148 SMs) and release g_proj via
// fence + counter; cluster blocks spin (by the time later waves run, the
// counter is long done). Head blocks stream independently, hiding proj.
// ---------------------------------------------------------------------------
__global__ void __launch_bounds__(FK_THREADS)
fused_kernel(const float* __restrict__ feature,
             const float* __restrict__ head_w,
             const float* __restrict__ t0p, const float* __restrict__ t0w,
             const float* __restrict__ t1p, const float* __restrict__ t1w,
             const float* __restrict__ t2p, const float* __restrict__ t2w,
             const float* __restrict__ t3p, const float* __restrict__ t3w) {
    __shared__ float sv[D];
    __shared__ float s_sum;
    const int tid = threadIdx.x, lane = tid & 31, warp = tid >> 5;
    const int bid = blockIdx.x;

    // ---------------- proj blocks ----------------
    if (bid < PROJ_BLOCKS) {
        const int row = bid * FK_WARPS + warp;    // 0..959
        const float* w;
        if      (row < 512) w = t0p + (size_t)row * D;
        else if (row < 768) w = t1p + (size_t)(row - 512) * D;
        else if (row < 896) w = t2p + (size_t)(row - 768) * D;
        else                w = t3p + (size_t)(row - 896) * D;

        const float4* w4 = (const float4*)w;
        const float4* f4 = (const float4*)feature;
        float acc = 0.f;
#pragma unroll
        for (int j = 0; j < 8; j++)
            acc += dot4(w4[lane + j * 32], f4[lane + j * 32]);
        acc = warp_sum(acc);
        if (lane == 0) g_proj[row] = acc;
        __syncthreads();
        if (tid == 0) {
            __threadfence();                      // release g_proj
            atomicAdd(&g_proj_ctr, 1);
        }
        return;
    }

    if (tid == 0) s_sum = 0.f;

    // ---------------- head blocks ----------------
    if (bid < CL_BASE) {
        for (int i = tid; i < D; i += FK_THREADS) sv[i] = feature[i];
        __syncthreads();
        int row = (bid - HEAD_BASE) * FK_WARPS + warp;
        if (row < NHEAD) {
            const float4* w4 = (const float4*)(head_w + (size_t)row * D);
            const float4* v4 = (const float4*)sv;
            float acc = 0.f;
#pragma unroll
            for (int j = 0; j < 8; j++)
                acc += dot4(w4[lane + j * 32], v4[lane + j * 32]);
            acc = warp_sum(acc);
            if (lane == 0) {
                g_head_logits[row] = acc;
                atomicAdd(&s_sum, __expf(acc));
            }
        }
        __syncthreads();
        if (tid == 0) atomicAdd(&g_sumexp[0], s_sum);
        return;
    }

    // ---------------- cluster blocks ----------------
    const int c0 = (bid - CL_BASE) * FK_WARPS;       // global chunk base
    int seg, lenf, proj_off, chunk;                  // chunk = segment-local
    const float* wmat;
    if (c0 < 10000)      { seg = 1; lenf = 512; wmat = t0w; chunk = c0 + warp;         proj_off = 0;   }
    else if (c0 < 20000) { seg = 2; lenf = 256; wmat = t1w; chunk = c0 - 10000 + warp; proj_off = 512; }
    else if (c0 < 30000) { seg = 3; lenf = 128; wmat = t2w; chunk = c0 - 20000 + warp; proj_off = 768; }
    else                 { seg = 4; lenf =  64; wmat = t3w; chunk = c0 - 30000 + warp; proj_off = 896; }

    // wait for proj producers (ordering via L2: producers fenced before ctr;
    // our proj reads below use __ldcg and issue only after ctr==60 observed)
    if (tid == 0) {
        while (*(volatile int*)&g_proj_ctr < PROJ_BLOCKS) { }
    }
    __syncthreads();
    for (int i = tid; i < lenf; i += FK_THREADS) sv[i] = __ldcg(&g_proj[proj_off + i]);
    __syncthreads();

    const bool valid = (c0 + warp) < CL_CHUNKS;      // only the last t3 block masks
    float a0 = 0.f, a1 = 0.f, a2 = 0.f, a3 = 0.f;
    if (valid) {
        const float4* w4 = (const float4*)wmat + (size_t)chunk * 128;
        const float4* v4 = (const float4*)sv;
        const int vm = (lenf >> 2) - 1;              // power-of-two mask
        float4 w0 = w4[lane];       float4 w1 = w4[lane + 32];
        float4 w2 = w4[lane + 64];  float4 w3 = w4[lane + 96];
        a0 = dot4(w0, v4[lane & vm]);
        a1 = dot4(w1, v4[(lane + 32) & vm]);
        a2 = dot4(w2, v4[(lane + 64) & vm]);
        a3 = dot4(w3, v4[(lane + 96) & vm]);

        float es = 0.f;
        if (seg == 1) {                       // 1 row/chunk
            float r = warp_sum(a0 + a1 + a2 + a3);
            if (lane == 0) { g_cl[chunk] = r; es = __expf(r); }
        } else if (seg == 2) {                // 2 rows/chunk
            float r0 = warp_sum(a0 + a1);
            float r1 = warp_sum(a2 + a3);
            if (lane == 0) {
                *(float2*)&g_cl[10000 + chunk * 2] = make_float2(r0, r1);
                es = __expf(r0) + __expf(r1);
            }
        } else if (seg == 3) {                // 4 rows/chunk
            float r0 = warp_sum(a0), r1 = warp_sum(a1);
            float r2 = warp_sum(a2), r3 = warp_sum(a3);
            if (lane == 0) {
                *(float4*)&g_cl[30000 + chunk * 4] = make_float4(r0, r1, r2, r3);
                es = __expf(r0) + __expf(r1) + __expf(r2) + __expf(r3);
            }
        } else {                              // 8 rows/chunk (16-lane halves)
            float h0 = half16_sum(a0), h1 = half16_sum(a1);
            float h2 = half16_sum(a2), h3 = half16_sum(a3);
            float o0 = __shfl_sync(0xffffffffu, h0, 16);
            float o1 = __shfl_sync(0xffffffffu, h1, 16);
            float o2 = __shfl_sync(0xffffffffu, h2, 16);
            float o3 = __shfl_sync(0xffffffffu, h3, 16);
            if (lane == 0) {
                float* p = &g_cl[70000 + chunk * 8];
                *(float4*)p       = make_float4(h0, o0, h1, o1);
                *(float4*)(p + 4) = make_float4(h2, o2, h3, o3);
                es = __expf(h0) + __expf(o0) + __expf(h1) + __expf(o1)
                   + __expf(h2) + __expf(o2) + __expf(h3) + __expf(o3);
            }
        }
        if (lane == 0) atomicAdd(&s_sum, es);
    }
    __syncthreads();
    if (tid == 0) atomicAdd(&g_sumexp[seg], s_sum);
}

// ---------------------------------------------------------------------------
// K2: gather targets, mean, negate; then reset counters for next replay
// ---------------------------------------------------------------------------
__global__ void __launch_bounds__(1024)
loss_kernel(const int* __restrict__ targets, float* __restrict__ out) {
    __shared__ float sh[32];
    __shared__ float s_lse[5];
    const int tid = threadIdx.x, lane = tid & 31, warp = tid >> 5;

    if (tid < 5) s_lse[tid] = logf(g_sumexp[tid]);
    __syncthreads();
    const float lse_h = s_lse[0];

    int4 t4 = ((const int4*)targets)[tid];   // 4096 / 1024 = 1 int4 each
    int ts[4] = {t4.x, t4.y, t4.z, t4.w};
    float local = 0.f;
#pragma unroll
    for (int k = 0; k < 4; k++) {
        int t = ts[k];
        float lp;
        if (t < SHORTLIST) {
            lp = g_head_logits[t] - lse_h;
        } else {
            int ci;
            if      (t < 20000) ci = 0;
            else if (t < 40000) ci = 1;
            else if (t < 80000) ci = 2;
            else                ci = 3;
            lp = g_cl[t - SHORTLIST] - s_lse[1 + ci]
               + g_head_logits[SHORTLIST + ci] - lse_h;
        }
        local += lp;
    }
    local = warp_sum(local);
    if (lane == 0) sh[warp] = local;
    __syncthreads();
    if (warp == 0) {
        float v = sh[lane];
        v = warp_sum(v);
        if (lane == 0) out[0] = -v / (float)NTGT;
    }

    // reset scratch for next graph replay (deterministic)
    if (tid == 0) g_proj_ctr = 0;
    if (tid < 5)  g_sumexp[tid] = 0.f;
}

// ---------------------------------------------------------------------------
extern "C" void kernel_launch(void* const* d_in, const int* in_sizes, int n_in,
                              void* d_out, int out_size) {
    const float* feature = (const float*)d_in[0];
    const int*   targets = (const int*)  d_in[1];
    const float* head_w  = (const float*)d_in[2];
    const float* t0p     = (const float*)d_in[3];
    const float* t0w     = (const float*)d_in[4];
    const float* t1p     = (const float*)d_in[5];
    const float* t1w     = (const float*)d_in[6];
    const float* t2p     = (const float*)d_in[7];
    const float* t2w     = (const float*)d_in[8];
    const float* t3p     = (const float*)d_in[9];
    const float* t3w     = (const float*)d_in[10];

    fused_kernel<<<NBLOCKS, FK_THREADS>>>(feature, head_w,
                                          t0p, t0w, t1p, t1w,
                                          t2p, t2w, t3p, t3w);
    loss_kernel<<<1, 1024>>>(targets, (float*)d_out);
}

// round 7
// speedup vs baseline: 2.0381x; 1.0338x over previous
#include <cuda_runtime.h>

#define D          1024
#define NHEAD      10004
#define SHORTLIST  10000
#define NPROJ      960
#define NCL        90000
#define NTGT       4096

#define FK_THREADS 512
#define FK_WARPS   16
#define PROJ_BLOCKS 60                                     // 960 rows / 16 warps
#define HEAD_BLOCKS ((NHEAD + FK_WARPS - 1) / FK_WARPS)    // 626
#define CL_CHUNKS   32500    // 10000 + 10000 + 10000 + 2500 (2KB chunks)
#define CL_BLOCKS   ((CL_CHUNKS + FK_WARPS - 1) / FK_WARPS) // 2032
#define HEAD_BASE   PROJ_BLOCKS
#define CL_BASE     (PROJ_BLOCKS + HEAD_BLOCKS)
#define NBLOCKS     (PROJ_BLOCKS + HEAD_BLOCKS + CL_BLOCKS)

#define LOSS_BLOCKS 32
#define LOSS_THREADS 128

// Scratch (allocation-free __device__ globals; reset by last loss block)
__device__ float g_head_logits[NHEAD];
__device__ float g_proj[NPROJ];
__device__ float g_cl[NCL];       // cluster logits, vocab order (t - 10000)
__device__ float g_sumexp[5];
__device__ int   g_proj_ctr;
__device__ int   g_loss_done;

__device__ __forceinline__ float warp_sum(float v) {
#pragma unroll
    for (int o = 16; o; o >>= 1) v += __shfl_xor_sync(0xffffffffu, v, o);
    return v;
}
__device__ __forceinline__ float half16_sum(float v) {   // reduce within 16-lane halves
#pragma unroll
    for (int o = 8; o; o >>= 1) v += __shfl_xor_sync(0xffffffffu, v, o);
    return v;
}
__device__ __forceinline__ float dot4(float4 a, float4 b) {
    return a.x * b.x + a.y * b.y + a.z * b.z + a.w * b.w;
}

// ---------------------------------------------------------------------------
// Fused kernel. Grid = [proj 60 | head 626 | cluster 2032] blocks, 512 thr.
// Proj blocks are wave-1 resident and release g_proj via fence + counter;
// head blocks stream independently (hiding proj); cluster blocks spin briefly.
// Block 0 also zeroes out[0] for the loss kernel's atomic accumulation.
// ---------------------------------------------------------------------------
__global__ void __launch_bounds__(FK_THREADS)
fused_kernel(const float* __restrict__ feature,
             const float* __restrict__ head_w,
             const float* __restrict__ t0p, const float* __restrict__ t0w,
             const float* __restrict__ t1p, const float* __restrict__ t1w,
             const float* __restrict__ t2p, const float* __restrict__ t2w,
             const float* __restrict__ t3p, const float* __restrict__ t3w,
             float* __restrict__ out) {
    __shared__ float sv[D];
    __shared__ float s_sum;
    const int tid = threadIdx.x, lane = tid & 31, warp = tid >> 5;
    const int bid = blockIdx.x;

    // ---------------- proj blocks ----------------
    if (bid < PROJ_BLOCKS) {
        if (bid == 0 && tid == 0) out[0] = 0.f;
        const int row = bid * FK_WARPS + warp;    // 0..959
        const float* w;
        if      (row < 512) w = t0p + (size_t)row * D;
        else if (row < 768) w = t1p + (size_t)(row - 512) * D;
        else if (row < 896) w = t2p + (size_t)(row - 768) * D;
        else                w = t3p + (size_t)(row - 896) * D;

        const float4* w4 = (const float4*)w;
        const float4* f4 = (const float4*)feature;
        float acc = 0.f;
#pragma unroll
        for (int j = 0; j < 8; j++)
            acc += dot4(w4[lane + j * 32], f4[lane + j * 32]);
        acc = warp_sum(acc);
        if (lane == 0) g_proj[row] = acc;
        __syncthreads();
        if (tid == 0) {
            __threadfence();                      // release g_proj
            atomicAdd(&g_proj_ctr, 1);
        }
        return;
    }

    if (tid == 0) s_sum = 0.f;

    // ---------------- head blocks ----------------
    if (bid < CL_BASE) {
        for (int i = tid; i < D; i += FK_THREADS) sv[i] = feature[i];
        __syncthreads();
        int row = (bid - HEAD_BASE) * FK_WARPS + warp;
        if (row < NHEAD) {
            const float4* w4 = (const float4*)(head_w + (size_t)row * D);
            const float4* v4 = (const float4*)sv;
            float acc = 0.f;
#pragma unroll
            for (int j = 0; j < 8; j++)
                acc += dot4(w4[lane + j * 32], v4[lane + j * 32]);
            acc = warp_sum(acc);
            if (lane == 0) {
                g_head_logits[row] = acc;
                atomicAdd(&s_sum, __expf(acc));
            }
        }
        __syncthreads();
        if (tid == 0) atomicAdd(&g_sumexp[0], s_sum);
        return;
    }

    // ---------------- cluster blocks ----------------
    const int c0 = (bid - CL_BASE) * FK_WARPS;       // global chunk base
    int seg, lenf, proj_off, chunk;                  // chunk = segment-local
    const float* wmat;
    if (c0 < 10000)      { seg = 1; lenf = 512; wmat = t0w; chunk = c0 + warp;         proj_off = 0;   }
    else if (c0 < 20000) { seg = 2; lenf = 256; wmat = t1w; chunk = c0 - 10000 + warp; proj_off = 512; }
    else if (c0 < 30000) { seg = 3; lenf = 128; wmat = t2w; chunk = c0 - 20000 + warp; proj_off = 768; }
    else                 { seg = 4; lenf =  64; wmat = t3w; chunk = c0 - 30000 + warp; proj_off = 896; }

    // wait for proj producers (release via fence+ctr; consume via __ldcg/L2)
    if (tid == 0) {
        while (*(volatile int*)&g_proj_ctr < PROJ_BLOCKS) { }
    }
    __syncthreads();
    for (int i = tid; i < lenf; i += FK_THREADS) sv[i] = __ldcg(&g_proj[proj_off + i]);
    __syncthreads();

    const bool valid = (c0 + warp) < CL_CHUNKS;      // only the last t3 block masks
    if (valid) {
        const float4* w4 = (const float4*)wmat + (size_t)chunk * 128;
        const float4* v4 = (const float4*)sv;
        const int vm = (lenf >> 2) - 1;              // power-of-two mask
        float4 w0 = w4[lane];       float4 w1 = w4[lane + 32];
        float4 w2 = w4[lane + 64];  float4 w3 = w4[lane + 96];
        float a0 = dot4(w0, v4[lane & vm]);
        float a1 = dot4(w1, v4[(lane + 32) & vm]);
        float a2 = dot4(w2, v4[(lane + 64) & vm]);
        float a3 = dot4(w3, v4[(lane + 96) & vm]);

        float es = 0.f;
        if (seg == 1) {                       // 1 row/chunk
            float r = warp_sum(a0 + a1 + a2 + a3);
            if (lane == 0) { g_cl[chunk] = r; es = __expf(r); }
        } else if (seg == 2) {                // 2 rows/chunk
            float r0 = warp_sum(a0 + a1);
            float r1 = warp_sum(a2 + a3);
            if (lane == 0) {
                *(float2*)&g_cl[10000 + chunk * 2] = make_float2(r0, r1);
                es = __expf(r0) + __expf(r1);
            }
        } else if (seg == 3) {                // 4 rows/chunk
            float r0 = warp_sum(a0), r1 = warp_sum(a1);
            float r2 = warp_sum(a2), r3 = warp_sum(a3);
            if (lane == 0) {
                *(float4*)&g_cl[30000 + chunk * 4] = make_float4(r0, r1, r2, r3);
                es = __expf(r0) + __expf(r1) + __expf(r2) + __expf(r3);
            }
        } else {                              // 8 rows/chunk (16-lane halves)
            float h0 = half16_sum(a0), h1 = half16_sum(a1);
            float h2 = half16_sum(a2), h3 = half16_sum(a3);
            float o0 = __shfl_sync(0xffffffffu, h0, 16);
            float o1 = __shfl_sync(0xffffffffu, h1, 16);
            float o2 = __shfl_sync(0xffffffffu, h2, 16);
            float o3 = __shfl_sync(0xffffffffu, h3, 16);
            if (lane == 0) {
                float* p = &g_cl[70000 + chunk * 8];
                *(float4*)p       = make_float4(h0, o0, h1, o1);
                *(float4*)(p + 4) = make_float4(h2, o2, h3, o3);
                es = __expf(h0) + __expf(o0) + __expf(h1) + __expf(o1)
                   + __expf(h2) + __expf(o2) + __expf(h3) + __expf(o3);
            }
        }
        if (lane == 0) atomicAdd(&s_sum, es);
    }
    __syncthreads();
    if (tid == 0) atomicAdd(&g_sumexp[seg], s_sum);
}

// ---------------------------------------------------------------------------
// K2: parallel gather-loss. 32 blocks x 128 threads = one target per thread.
// Partials accumulate into out[0] (zeroed by fused_kernel). Last block resets
// scratch for the next graph replay.
// ---------------------------------------------------------------------------
__global__ void __launch_bounds__(LOSS_THREADS)
loss_kernel(const int* __restrict__ targets, float* __restrict__ out) {
    __shared__ float s_lse[5];
    __shared__ float sh[4];
    const int tid = threadIdx.x, lane = tid & 31, warp = tid >> 5;

    if (tid < 5) s_lse[tid] = logf(g_sumexp[tid]);
    __syncthreads();
    const float lse_h = s_lse[0];

    const int t = targets[blockIdx.x * LOSS_THREADS + tid];
    float lp;
    if (t < SHORTLIST) {
        lp = g_head_logits[t] - lse_h;
    } else {
        int ci;
        if      (t < 20000) ci = 0;
        else if (t < 40000) ci = 1;
        else if (t < 80000) ci = 2;
        else                ci = 3;
        lp = g_cl[t - SHORTLIST] - s_lse[1 + ci]
           + g_head_logits[SHORTLIST + ci] - lse_h;
    }

    float local = warp_sum(lp);
    if (lane == 0) sh[warp] = local;
    __syncthreads();
    if (tid == 0) {
        float v = sh[0] + sh[1] + sh[2] + sh[3];
        atomicAdd(out, -v * (1.0f / NTGT));
        // last block resets scratch (all blocks already consumed g_sumexp)
        int old = atomicAdd(&g_loss_done, 1);
        if (old == LOSS_BLOCKS - 1) {
            g_loss_done = 0;
            g_proj_ctr  = 0;
            g_sumexp[0] = 0.f; g_sumexp[1] = 0.f; g_sumexp[2] = 0.f;
            g_sumexp[3] = 0.f; g_sumexp[4] = 0.f;
        }
    }
}

// ---------------------------------------------------------------------------
extern "C" void kernel_launch(void* const* d_in, const int* in_sizes, int n_in,
                              void* d_out, int out_size) {
    const float* feature = (const float*)d_in[0];
    const int*   targets = (const int*)  d_in[1];
    const float* head_w  = (const float*)d_in[2];
    const float* t0p     = (const float*)d_in[3];
    const float* t0w     = (const float*)d_in[4];
    const float* t1p     = (const float*)d_in[5];
    const float* t1w     = (const float*)d_in[6];
    const float* t2p     = (const float*)d_in[7];
    const float* t2w     = (const float*)d_in[8];
    const float* t3p     = (const float*)d_in[9];
    const float* t3w     = (const float*)d_in[10];

    fused_kernel<<<NBLOCKS, FK_THREADS>>>(feature, head_w,
                                          t0p, t0w, t1p, t1w,
                                          t2p, t2w, t3p, t3w,
                                          (float*)d_out);
    loss_kernel<<<LOSS_BLOCKS, LOSS_THREADS>>>(targets, (float*)d_out);
}